// round 1
// baseline (speedup 1.0000x reference)
#include <cuda_runtime.h>
#include <math.h>

#define BB 8
#define AA 64
#define DE 128
#define MM 512
#define DH 64
#define ZD 128

// Scratch (device globals: allocation-free rule)
__device__ float g_dH2[BB * MM];
__device__ float g_logv[BB * MM * DH];

__device__ __forceinline__ float warp_sum(float v) {
#pragma unroll
    for (int o = 16; o > 0; o >>= 1) v += __shfl_xor_sync(0xffffffffu, v, o);
    return v;
}

// ---------------------------------------------------------------------------
// Prologue: per (b,m) compute Poincare dH2 and log-map vector (shared u term).
// One warp per (b,m); lane l owns dims 2l, 2l+1 of dh=64.
// ---------------------------------------------------------------------------
__global__ void __launch_bounds__(256) prologue_kernel(
    const float* __restrict__ currH,   // [B, DH]
    const float* __restrict__ demoH)   // [B*M, DH]
{
    int gw = blockIdx.x * 8 + (threadIdx.x >> 5);
    int l = threadIdx.x & 31;
    if (gw >= BB * MM) return;
    int b = gw >> 9;   // M = 512

    float x0 = currH[b * DH + 2 * l], x1 = currH[b * DH + 2 * l + 1];
    float y0 = demoH[(size_t)gw * DH + 2 * l], y1 = demoH[(size_t)gw * DH + 2 * l + 1];

    const float thr = 1.0f - 1e-5f;
    // project x to ball
    float x2 = warp_sum(x0 * x0 + x1 * x1);
    float nx = fmaxf(sqrtf(x2), 1e-15f);
    if (nx > thr) { float s = thr / nx; x0 *= s; x1 *= s; x2 *= s * s; }
    // project y to ball
    float y2 = warp_sum(y0 * y0 + y1 * y1);
    float ny = fmaxf(sqrtf(y2), 1e-15f);
    if (ny > thr) { float s = thr / ny; y0 *= s; y1 *= s; y2 *= s * s; }

    float xy = warp_sum(x0 * y0 + x1 * y1);

    // u = mobius_add(-x, y), c = 1
    float Ac = 1.0f - 2.0f * xy + y2;          // coeff for (-x)
    float Bc = 1.0f - x2;                      // coeff for y
    float den = fmaxf(1.0f - 2.0f * xy + x2 * y2, 1e-15f);
    float inv = 1.0f / den;
    float u0 = (Bc * y0 - Ac * x0) * inv;
    float u1 = (Bc * y1 - Ac * x1) * inv;

    float un2 = warp_sum(u0 * u0 + u1 * u1);
    float un = fmaxf(sqrtf(un2), 1e-15f);
    float arg = fminf(un, 1.0f - 1e-7f);
    float at = atanhf(arg);

    if (l == 0) g_dH2[gw] = 4.0f * at * at;    // (2*atanh)^2

    // log map: scale = (2/lam)*atanh = clip(1-x2,1e-15)*atanh ; times u/|u|
    float sc = fmaxf(1.0f - x2, 1e-15f) * at / un;
    g_logv[(size_t)gw * DH + 2 * l]     = sc * u0;
    g_logv[(size_t)gw * DH + 2 * l + 1] = sc * u1;
}

// ---------------------------------------------------------------------------
// Main: one CTA per (b,a). 16 warps, warp w owns m = w + 16j (j<32), unroll 4.
// Online softmax over m with fused Euclidean + hyperbolic aggregation,
// then exp-map, GEMVs with We/Wh, LayerNorm — single read of demo_rho.
// ---------------------------------------------------------------------------
__global__ void __launch_bounds__(512) main_kernel(
    const float* __restrict__ curr_rho,  // [B, A, DE]
    const float* __restrict__ currH,     // [B, DH]
    const float* __restrict__ demo_rho,  // [B, M, A, DE]
    const float* __restrict__ We,        // [64, DE]
    const float* __restrict__ Wh,        // [64, DH]
    const float* __restrict__ gamma,     // [ZD]
    const float* __restrict__ beta,      // [ZD]
    float* __restrict__ out)             // [B, A, ZD]
{
    const int bx = blockIdx.x;           // b*AA + a
    const int b = bx >> 6, a = bx & 63;
    const int tid = threadIdx.x;
    const int w = tid >> 5, l = tid & 31;

    __shared__ float s_mx[16], s_sm[16];
    __shared__ float s_acce[16][DE];
    __shared__ float s_accv[16][DH];
    __shared__ float s_eout[DE];
    __shared__ float s_v[DH];
    __shared__ float s_h[DH];
    __shared__ float s_red[8];

    const float4* dbase = reinterpret_cast<const float4*>(demo_rho)
                          + ((size_t)b * MM * AA + a) * (DE / 4) + l;
    const float4 cur = reinterpret_cast<const float4*>(curr_rho)[(size_t)bx * (DE / 4) + l];
    const float* dh2p = g_dH2 + b * MM;
    const float* lvp = g_logv + (size_t)b * MM * DH;

    float mx = -3.0e38f, sm = 0.f;
    float4 ae = make_float4(0.f, 0.f, 0.f, 0.f);
    float av0 = 0.f, av1 = 0.f;

    for (int j = 0; j < 32; j += 4) {
        float4 dm[4]; float h2[4]; float2 lv[4];
#pragma unroll
        for (int k = 0; k < 4; k++) {
            int m = w + 16 * (j + k);
            dm[k] = dbase[(size_t)m * (AA * DE / 4)];
            h2[k] = __ldg(dh2p + m);
            lv[k] = reinterpret_cast<const float2*>(lvp + (size_t)m * DH)[l];
        }
        float s[4];
#pragma unroll
        for (int k = 0; k < 4; k++) {
            float d0 = cur.x - dm[k].x, d1 = cur.y - dm[k].y;
            float d2 = cur.z - dm[k].z, d3 = cur.w - dm[k].w;
            s[k] = d0 * d0 + d1 * d1 + d2 * d2 + d3 * d3;
        }
#pragma unroll
        for (int o = 16; o > 0; o >>= 1) {
#pragma unroll
            for (int k = 0; k < 4; k++) s[k] += __shfl_xor_sync(0xffffffffu, s[k], o);
        }
#pragma unroll
        for (int k = 0; k < 4; k++) {
            float sc = -(s[k] + h2[k]);          // score (warp-uniform)
            if (sc > mx) {
                float c = __expf(mx - sc);
                mx = sc;
                sm = sm * c + 1.0f;
                ae.x = ae.x * c + dm[k].x; ae.y = ae.y * c + dm[k].y;
                ae.z = ae.z * c + dm[k].z; ae.w = ae.w * c + dm[k].w;
                av0 = av0 * c + lv[k].x;   av1 = av1 * c + lv[k].y;
            } else {
                float p = __expf(sc - mx);
                sm += p;
                ae.x += p * dm[k].x; ae.y += p * dm[k].y;
                ae.z += p * dm[k].z; ae.w += p * dm[k].w;
                av0 += p * lv[k].x;  av1 += p * lv[k].y;
            }
        }
    }

    if (l == 0) { s_mx[w] = mx; s_sm[w] = sm; }
    *reinterpret_cast<float4*>(&s_acce[w][4 * l]) = ae;
    s_accv[w][2 * l] = av0; s_accv[w][2 * l + 1] = av1;
    __syncthreads();

    // merge 16 partial softmax states
    float gmax = -3.0e38f;
#pragma unroll
    for (int q = 0; q < 16; q++) gmax = fmaxf(gmax, s_mx[q]);
    float S = 0.f;
#pragma unroll
    for (int q = 0; q < 16; q++) S += __expf(s_mx[q] - gmax) * s_sm[q];
    float invS = 1.0f / S;

    if (tid < DE) {
        float e = 0.f;
#pragma unroll
        for (int q = 0; q < 16; q++) e += __expf(s_mx[q] - gmax) * s_acce[q][tid];
        s_eout[tid] = e * invS;
    } else if (tid < DE + DH) {
        int d = tid - DE;
        float v = 0.f;
#pragma unroll
        for (int q = 0; q < 16; q++) v += __expf(s_mx[q] - gmax) * s_accv[q][d];
        s_v[d] = v * invS;
    }
    __syncthreads();

    // exp-map on warp 0 (lane l owns dims 2l, 2l+1)
    if (w == 0) {
        float x0 = currH[b * DH + 2 * l], x1 = currH[b * DH + 2 * l + 1];
        const float thr = 1.0f - 1e-5f;
        float x2 = warp_sum(x0 * x0 + x1 * x1);
        float nx = fmaxf(sqrtf(x2), 1e-15f);
        if (nx > thr) { float s0 = thr / nx; x0 *= s0; x1 *= s0; x2 *= s0 * s0; }
        float lam = 2.0f / fmaxf(1.0f - x2, 1e-15f);

        float v0 = s_v[2 * l], v1 = s_v[2 * l + 1];
        float vn2 = warp_sum(v0 * v0 + v1 * v1);
        float vn = fmaxf(sqrtf(vn2), 1e-15f);
        float fac = tanhf(lam * vn * 0.5f);
        float iv = fac / vn;
        float y0 = v0 * iv, y1 = v1 * iv;

        float yn2 = warp_sum(y0 * y0 + y1 * y1);
        float yn = fmaxf(sqrtf(yn2), 1e-15f);
        if (yn > thr) { float s0 = thr / yn; y0 *= s0; y1 *= s0; yn2 *= s0 * s0; }

        float xy = warp_sum(x0 * y0 + x1 * y1);
        float den = fmaxf(1.0f + 2.0f * xy + x2 * yn2, 1e-15f);
        float ca = (1.0f + 2.0f * xy + yn2) / den;
        float cb = (1.0f - x2) / den;
        float o0 = ca * x0 + cb * y0, o1 = ca * x1 + cb * y1;

        float on2 = warp_sum(o0 * o0 + o1 * o1);
        float on = fmaxf(sqrtf(on2), 1e-15f);
        if (on > thr) { float s0 = thr / on; o0 *= s0; o1 *= s0; }
        s_h[2 * l] = o0; s_h[2 * l + 1] = o1;
    }
    __syncthreads();

    // GEMVs + LayerNorm (threads 0..127 produce z[j])
    float zj = 0.f;
    if (tid < ZD) {
        if (tid < 64) {
            const float* wr = We + tid * DE;
#pragma unroll 8
            for (int d = 0; d < DE; d++) zj += wr[d] * s_eout[d];
        } else {
            const float* wr = Wh + (tid - 64) * DH;
#pragma unroll 8
            for (int d = 0; d < DH; d++) zj += wr[d] * s_h[d];
        }
        float p1 = warp_sum(zj);
        float p2 = warp_sum(zj * zj);
        if (l == 0) { s_red[w] = p1; s_red[4 + w] = p2; }
    }
    __syncthreads();
    if (tid < ZD) {
        float sum = s_red[0] + s_red[1] + s_red[2] + s_red[3];
        float sq  = s_red[4] + s_red[5] + s_red[6] + s_red[7];
        float mean = sum * (1.0f / ZD);
        float var = sq * (1.0f / ZD) - mean * mean;
        float r = rsqrtf(var + 1e-5f);
        out[(size_t)bx * ZD + tid] = (zj - mean) * r * gamma[tid] + beta[tid];
    }
}

extern "C" void kernel_launch(void* const* d_in, const int* in_sizes, int n_in,
                              void* d_out, int out_size) {
    const float* curr_rho = (const float*)d_in[0];
    const float* currH    = (const float*)d_in[1];
    const float* demo_rho = (const float*)d_in[2];
    const float* demoH    = (const float*)d_in[3];
    const float* We       = (const float*)d_in[4];
    const float* Wh       = (const float*)d_in[5];
    const float* gamma    = (const float*)d_in[6];
    const float* beta     = (const float*)d_in[7];
    float* out = (float*)d_out;

    prologue_kernel<<<512, 256>>>(currH, demoH);
    main_kernel<<<BB * AA, 512>>>(curr_rho, currH, demo_rho, We, Wh, gamma, beta, out);
}